// round 2
// baseline (speedup 1.0000x reference)
#include <cuda_runtime.h>
#include <math.h>

#define TT 512
#define BB 128
#define II 256
#define HH 1024
#define GG 4096   // 4*HH
#define NCTA 128  // persistent recurrence grid (1 CTA/SM, all co-resident)

// ---------------- scratch (device globals: no allocations allowed) ----------
__device__ float g_xproj[(size_t)TT * BB * GG];   // 1.07 GB: x@Wxh^T + bxh
__device__ float g_hs[(size_t)TT * BB * HH];      // 268 MB: all hidden states
__device__ float g_h2[2 * BB * HH];               // double-buffered h
__device__ unsigned g_bar_count;                  // zero-init; returns to 0 each barrier
__device__ volatile unsigned g_bar_gen;           // monotonic generation

// ---------------- packed f32x2 helpers (2x FFMA throughput on sm_103a) ------
__device__ __forceinline__ unsigned long long pack2(float lo, float hi) {
    unsigned long long r;
    asm("mov.b64 %0, {%1, %2};" : "=l"(r) : "f"(lo), "f"(hi));
    return r;
}
__device__ __forceinline__ void unpack2(unsigned long long v, float& lo, float& hi) {
    asm("mov.b64 {%0, %1}, %2;" : "=f"(lo), "=f"(hi) : "l"(v));
}
__device__ __forceinline__ void ffma2(unsigned long long& d,
                                      unsigned long long a,
                                      unsigned long long b) {
    asm("fma.rn.f32x2 %0, %1, %2, %0;" : "+l"(d) : "l"(a), "l"(b));
}

__device__ __forceinline__ float fsig(float x) {
    return __fdividef(1.0f, 1.0f + __expf(-x));
}
__device__ __forceinline__ float ftanh(float x) {
    return __fdividef(2.0f, 1.0f + __expf(-2.0f * x)) - 1.0f;
}

// ---------------- software grid barrier (all NCTA CTAs co-resident) ---------
__device__ __forceinline__ void grid_sync() {
    __syncthreads();
    if (threadIdx.x == 0) {
        __threadfence();
        unsigned g = g_bar_gen;
        unsigned old = atomicInc(&g_bar_count, NCTA - 1);
        if (old == NCTA - 1) {
            __threadfence();
            g_bar_gen = g + 1;          // release
        } else {
            while (g_bar_gen == g) { }  // spin on L2
            __threadfence();
        }
    }
    __syncthreads();
}

// ---------------- generic fp32 GEMM: C[m,n] = sum_k A[m,k]*W[n,k] + bias[n]
template<int BM, int TM>
__global__ __launch_bounds__(256) void gemm_f32(
    const float* __restrict__ A, const float* __restrict__ W,
    const float* __restrict__ bias,
    float* __restrict__ C, int M, int N, int K)
{
    constexpr int BN = 64, BK = 16, TN = 4;
    __shared__ float As[BK][BM];
    __shared__ float Bs[BK][BN];

    const int tid = threadIdx.x;
    const int tx = tid & 15;    // -> n
    const int ty = tid >> 4;    // -> m
    const int nb = blockIdx.x * BN;
    const int mb = blockIdx.y * BM;

    unsigned long long acc[TM / 2][TN];
#pragma unroll
    for (int i = 0; i < TM / 2; i++)
#pragma unroll
        for (int j = 0; j < TN; j++) acc[i][j] = 0ull;

    for (int k0 = 0; k0 < K; k0 += BK) {
#pragma unroll
        for (int i = 0; i < BM / 64; i++) {
            int idx = tid + i * 256;
            int r = idx >> 2;
            int kq = (idx & 3) << 2;
            float4 v = *reinterpret_cast<const float4*>(A + (size_t)(mb + r) * K + k0 + kq);
            As[kq + 0][r] = v.x; As[kq + 1][r] = v.y;
            As[kq + 2][r] = v.z; As[kq + 3][r] = v.w;
        }
        {
            int r = tid >> 2;
            int kq = (tid & 3) << 2;
            float4 v = *reinterpret_cast<const float4*>(W + (size_t)(nb + r) * K + k0 + kq);
            Bs[kq + 0][r] = v.x; Bs[kq + 1][r] = v.y;
            Bs[kq + 2][r] = v.z; Bs[kq + 3][r] = v.w;
        }
        __syncthreads();

#pragma unroll
        for (int k = 0; k < BK; k++) {
            unsigned long long a2[TM / 2];
#pragma unroll
            for (int i = 0; i < TM / 2; i++)
                a2[i] = *reinterpret_cast<const unsigned long long*>(&As[k][ty * TM + 2 * i]);
            float4 bv = *reinterpret_cast<const float4*>(&Bs[k][tx * TN]);
            unsigned long long b2[TN];
            b2[0] = pack2(bv.x, bv.x);
            b2[1] = pack2(bv.y, bv.y);
            b2[2] = pack2(bv.z, bv.z);
            b2[3] = pack2(bv.w, bv.w);
#pragma unroll
            for (int i = 0; i < TM / 2; i++)
#pragma unroll
                for (int j = 0; j < TN; j++)
                    ffma2(acc[i][j], a2[i], b2[j]);
        }
        __syncthreads();
    }

    const int n0 = nb + tx * TN;
    float4 bias4 = *reinterpret_cast<const float4*>(bias + n0);
#pragma unroll
    for (int i = 0; i < TM / 2; i++) {
        int m0 = mb + ty * TM + 2 * i;
        float lo[TN], hi[TN];
#pragma unroll
        for (int j = 0; j < TN; j++) unpack2(acc[i][j], lo[j], hi[j]);
        float4 r0 = make_float4(lo[0] + bias4.x, lo[1] + bias4.y,
                                lo[2] + bias4.z, lo[3] + bias4.w);
        float4 r1 = make_float4(hi[0] + bias4.x, hi[1] + bias4.y,
                                hi[2] + bias4.z, hi[3] + bias4.w);
        *reinterpret_cast<float4*>(C + (size_t)m0 * N + n0) = r0;
        *reinterpret_cast<float4*>(C + (size_t)(m0 + 1) * N + n0) = r1;
    }
}

// ---------------- persistent LSTM recurrence --------------------------------
// Grid: 128 CTAs x 128 threads. CTA owns hidden cols [j0, j0+8) for ALL batch
// rows. Whh slice (32 gate-rows x 1024) lives in smem for all 512 steps.
// c lives in registers. h double-buffered in gmem; one grid barrier per step.
__global__ void __launch_bounds__(128, 1) lstm_recur(
    const float* __restrict__ xproj, const float* __restrict__ Whh,
    const float* __restrict__ bhh, float* __restrict__ hs)
{
    extern __shared__ float sm[];
    float* Wsh = sm;                     // [1024][32]  (k-major, col = g*8+jj)
    float* Hsh = sm + 1024 * 32;         // 2 x [16][128]

    const int tid = threadIdx.x;
    const int tx = tid & 7;              // jj within block
    const int ty = tid >> 3;             // 0..15 -> rows ty*8 .. ty*8+7
    const int j0 = blockIdx.x * 8;
    const int j  = j0 + tx;

    // --- load Whh slice into smem, transposed: Wsh[k][g*8+jj] = Whh[g*1024+j0+jj][k]
    {
        int gcl = tid & 31;              // 0..31
        int g = gcl >> 3, jj = gcl & 7;
        const float* wr = Whh + (size_t)(g * HH + j0 + jj) * HH;
        int kbase = (tid >> 5) * 256;    // 4 warps x 256 k each
        for (int q = 0; q < 64; q++) {
            int k = kbase + q * 4;
            float4 v = *reinterpret_cast<const float4*>(wr + k);
            Wsh[(k + 0) * 32 + gcl] = v.x;
            Wsh[(k + 1) * 32 + gcl] = v.y;
            Wsh[(k + 2) * 32 + gcl] = v.z;
            Wsh[(k + 3) * 32 + gcl] = v.w;
        }
    }

    float bg[4];
#pragma unroll
    for (int g = 0; g < 4; g++) bg[g] = bhh[g * HH + j];

    float c[8];
#pragma unroll
    for (int i = 0; i < 8; i++) c[i] = 0.0f;
    // zero h buffer 0 (owned cells)
#pragma unroll
    for (int i = 0; i < 8; i++) g_h2[(size_t)(ty * 8 + i) * HH + j] = 0.0f;

    grid_sync();   // h0 + Wsh visible everywhere

    for (int t = 0; t < TT; t++) {
        const float* hp = g_h2 + (size_t)(t & 1) * (BB * HH);
        float*       hn = g_h2 + (size_t)((t + 1) & 1) * (BB * HH);

        unsigned long long acc[4][4];
#pragma unroll
        for (int i = 0; i < 4; i++)
#pragma unroll
            for (int g = 0; g < 4; g++) acc[i][g] = 0ull;

        // prefetch chunk 0: thread tid owns batch row b = tid
        const float* hr = hp + (size_t)tid * HH;
        float4 pf0 = *reinterpret_cast<const float4*>(hr + 0);
        float4 pf1 = *reinterpret_cast<const float4*>(hr + 4);
        float4 pf2 = *reinterpret_cast<const float4*>(hr + 8);
        float4 pf3 = *reinterpret_cast<const float4*>(hr + 12);

        for (int kc = 0; kc < 64; kc++) {
            float* HB = Hsh + (kc & 1) * (16 * 128);
            // stage (transposed): HB[k][b]
            HB[ 0 * 128 + tid] = pf0.x; HB[ 1 * 128 + tid] = pf0.y;
            HB[ 2 * 128 + tid] = pf0.z; HB[ 3 * 128 + tid] = pf0.w;
            HB[ 4 * 128 + tid] = pf1.x; HB[ 5 * 128 + tid] = pf1.y;
            HB[ 6 * 128 + tid] = pf1.z; HB[ 7 * 128 + tid] = pf1.w;
            HB[ 8 * 128 + tid] = pf2.x; HB[ 9 * 128 + tid] = pf2.y;
            HB[10 * 128 + tid] = pf2.z; HB[11 * 128 + tid] = pf2.w;
            HB[12 * 128 + tid] = pf3.x; HB[13 * 128 + tid] = pf3.y;
            HB[14 * 128 + tid] = pf3.z; HB[15 * 128 + tid] = pf3.w;
            if (kc < 63) {
                const float* hr2 = hp + (size_t)tid * HH + (kc + 1) * 16;
                pf0 = *reinterpret_cast<const float4*>(hr2 + 0);
                pf1 = *reinterpret_cast<const float4*>(hr2 + 4);
                pf2 = *reinterpret_cast<const float4*>(hr2 + 8);
                pf3 = *reinterpret_cast<const float4*>(hr2 + 12);
            }
            __syncthreads();

            const float* wkb = Wsh + kc * 16 * 32;
#pragma unroll
            for (int k = 0; k < 16; k++) {
                const float* arow = HB + k * 128 + ty * 8;
                unsigned long long a0 = *reinterpret_cast<const unsigned long long*>(arow + 0);
                unsigned long long a1 = *reinterpret_cast<const unsigned long long*>(arow + 2);
                unsigned long long a2v = *reinterpret_cast<const unsigned long long*>(arow + 4);
                unsigned long long a3 = *reinterpret_cast<const unsigned long long*>(arow + 6);
                const float* wk = wkb + k * 32;
                float w0 = wk[tx], w1 = wk[8 + tx], w2 = wk[16 + tx], w3 = wk[24 + tx];
                unsigned long long b0 = pack2(w0, w0);
                unsigned long long b1 = pack2(w1, w1);
                unsigned long long b2 = pack2(w2, w2);
                unsigned long long b3 = pack2(w3, w3);
                ffma2(acc[0][0], a0, b0); ffma2(acc[0][1], a0, b1);
                ffma2(acc[0][2], a0, b2); ffma2(acc[0][3], a0, b3);
                ffma2(acc[1][0], a1, b0); ffma2(acc[1][1], a1, b1);
                ffma2(acc[1][2], a1, b2); ffma2(acc[1][3], a1, b3);
                ffma2(acc[2][0], a2v, b0); ffma2(acc[2][1], a2v, b1);
                ffma2(acc[2][2], a2v, b2); ffma2(acc[2][3], a2v, b3);
                ffma2(acc[3][0], a3, b0); ffma2(acc[3][1], a3, b1);
                ffma2(acc[3][2], a3, b2); ffma2(acc[3][3], a3, b3);
            }
            // no trailing sync needed: next STS targets the other Hsh buffer,
            // and grid_sync() at step end syncs before buffer reuse wraps.
        }

        // --- epilogue + pointwise ---
        const float* xp = xproj + (size_t)t * BB * GG;
        float* hst = hs + (size_t)t * BB * HH;
#pragma unroll
        for (int i2 = 0; i2 < 4; i2++) {
            int b0r = ty * 8 + 2 * i2;
            int b1r = b0r + 1;
            const float* xp0 = xp + (size_t)b0r * GG + j;
            const float* xp1 = xp + (size_t)b1r * GG + j;
            float gl[4], gh[4];
#pragma unroll
            for (int g = 0; g < 4; g++) {
                float lo, hi;
                unpack2(acc[i2][g], lo, hi);
                gl[g] = lo + xp0[(size_t)g * HH] + bg[g];
                gh[g] = hi + xp1[(size_t)g * HH] + bg[g];
            }
            {
                float ig = fsig(gl[0]), fg = fsig(gl[1]);
                float gv = ftanh(gl[2]), og = fsig(gl[3]);
                float cn = fg * c[2 * i2] + ig * gv;
                c[2 * i2] = cn;
                float hv = og * ftanh(cn);
                hn[(size_t)b0r * HH + j] = hv;
                hst[(size_t)b0r * HH + j] = hv;
            }
            {
                float ig = fsig(gh[0]), fg = fsig(gh[1]);
                float gv = ftanh(gh[2]), og = fsig(gh[3]);
                float cn = fg * c[2 * i2 + 1] + ig * gv;
                c[2 * i2 + 1] = cn;
                float hv = og * ftanh(cn);
                hn[(size_t)b1r * HH + j] = hv;
                hst[(size_t)b1r * HH + j] = hv;
            }
        }
        grid_sync();
    }
}

// ---------------- row-wise log_softmax over last dim (II=256), in place -----
__global__ void log_softmax_k(float* __restrict__ out) {
    int row = blockIdx.x;
    float* p = out + (size_t)row * II;
    int tid = threadIdx.x;
    int lane = tid & 31, wid = tid >> 5;
    float v = p[tid];

    __shared__ float redm[8];
    __shared__ float reds[8];

    float m = v;
#pragma unroll
    for (int o = 16; o > 0; o >>= 1) m = fmaxf(m, __shfl_xor_sync(0xffffffffu, m, o));
    if (lane == 0) redm[wid] = m;
    __syncthreads();
    float mx = redm[0];
#pragma unroll
    for (int i = 1; i < 8; i++) mx = fmaxf(mx, redm[i]);

    float e = expf(v - mx);
    float s = e;
#pragma unroll
    for (int o = 16; o > 0; o >>= 1) s += __shfl_xor_sync(0xffffffffu, s, o);
    if (lane == 0) reds[wid] = s;
    __syncthreads();
    float tot = 0.0f;
#pragma unroll
    for (int i = 0; i < 8; i++) tot += reds[i];

    p[tid] = v - mx - logf(tot);
}

// ---------------- launch (4 graph nodes total) ------------------------------
extern "C" void kernel_launch(void* const* d_in, const int* in_sizes, int n_in,
                              void* d_out, int out_size)
{
    const float* inp  = (const float*)d_in[0];   // [512,128,256]
    const float* Wxh  = (const float*)d_in[1];   // [4096,256]
    const float* bxh  = (const float*)d_in[2];   // [4096]
    const float* Whh  = (const float*)d_in[3];   // [4096,1024]
    const float* bhh  = (const float*)d_in[4];   // [4096]
    const float* Wout = (const float*)d_in[5];   // [256,1024]
    const float* bout = (const float*)d_in[6];   // [256]
    float* out = (float*)d_out;                  // [512,128,256]

    float *xproj, *hs;
    cudaGetSymbolAddress((void**)&xproj, g_xproj);
    cudaGetSymbolAddress((void**)&hs,    g_hs);

    static bool attr_set = false;
    if (!attr_set) {
        cudaFuncSetAttribute(lstm_recur,
                             cudaFuncAttributeMaxDynamicSharedMemorySize,
                             (1024 * 32 + 2 * 16 * 128) * 4);
        attr_set = true;
    }

    // 1) x projection for all timesteps: [T*B, 4H] = [T*B, IN] @ Wxh^T + bxh
    gemm_f32<128, 8><<<dim3(GG / 64, (TT * BB) / 128), 256>>>(
        inp, Wxh, bxh, xproj, TT * BB, GG, II);

    // 2) persistent recurrence (all 512 steps in one kernel)
    lstm_recur<<<NCTA, 128, (1024 * 32 + 2 * 16 * 128) * 4>>>(xproj, Whh, bhh, hs);

    // 3) output projection: [T*B, IN] = hs @ Wout^T + bout (into d_out)
    gemm_f32<128, 8><<<dim3(II / 64, (TT * BB) / 128), 256>>>(
        hs, Wout, bout, out, TT * BB, II, HH);

    // 4) in-place log_softmax over last dim
    log_softmax_k<<<TT * BB, 256>>>(out);
}

// round 6
// speedup vs baseline: 1.7130x; 1.7130x over previous
#include <cuda_runtime.h>
#include <cuda_bf16.h>
#include <math.h>
#include <stdint.h>

#define TT 512
#define BB 128
#define II 256
#define HH 1024
#define GG 4096   // 4*HH
#define NCTA 128  // persistent recurrence grid (1 CTA/SM, all co-resident)

// ---------------- scratch (device globals: no allocations allowed) ----------
__device__ float g_xproj[(size_t)TT * BB * GG];   // 1.07 GB: x@Wxh^T + bxh
__device__ float g_hs[(size_t)TT * BB * HH];      // 268 MB: all hidden states
__device__ unsigned short g_hhi[2 * BB * HH];     // h hi bf16, double-buffered
__device__ unsigned short g_hlo[2 * BB * HH];     // h lo bf16, double-buffered
__device__ unsigned g_bar_count;
__device__ volatile unsigned g_bar_gen;

// ---------------- packed f32x2 helpers (for fp32 SIMT GEMMs) ----------------
__device__ __forceinline__ unsigned long long pack2(float lo, float hi) {
    unsigned long long r;
    asm("mov.b64 %0, {%1, %2};" : "=l"(r) : "f"(lo), "f"(hi));
    return r;
}
__device__ __forceinline__ void unpack2(unsigned long long v, float& lo, float& hi) {
    asm("mov.b64 {%0, %1}, %2;" : "=f"(lo), "=f"(hi) : "l"(v));
}
__device__ __forceinline__ void ffma2(unsigned long long& d,
                                      unsigned long long a,
                                      unsigned long long b) {
    asm("fma.rn.f32x2 %0, %1, %2, %0;" : "+l"(d) : "l"(a), "l"(b));
}

__device__ __forceinline__ float fsig(float x) {
    return __fdividef(1.0f, 1.0f + __expf(-x));
}
__device__ __forceinline__ float ftanh(float x) {
    return __fdividef(2.0f, 1.0f + __expf(-2.0f * x)) - 1.0f;
}

// ---------------- tensor-core primitives ------------------------------------
__device__ __forceinline__ uint32_t s2u(const void* p) {
    return (uint32_t)__cvta_generic_to_shared(p);
}
__device__ __forceinline__ void ldsm_x4(uint32_t* r, uint32_t a) {
    asm volatile("ldmatrix.sync.aligned.m8n8.x4.shared.b16 {%0,%1,%2,%3}, [%4];"
                 : "=r"(r[0]), "=r"(r[1]), "=r"(r[2]), "=r"(r[3]) : "r"(a));
}
__device__ __forceinline__ void ldsm_x4_t(uint32_t* r, uint32_t a) {
    asm volatile("ldmatrix.sync.aligned.m8n8.x4.trans.shared.b16 {%0,%1,%2,%3}, [%4];"
                 : "=r"(r[0]), "=r"(r[1]), "=r"(r[2]), "=r"(r[3]) : "r"(a));
}
__device__ __forceinline__ void mma_bf16(float* c, const uint32_t* a, const uint32_t* b) {
    asm volatile("mma.sync.aligned.m16n8k16.row.col.f32.bf16.bf16.f32 "
                 "{%0,%1,%2,%3}, {%4,%5,%6,%7}, {%8,%9}, {%0,%1,%2,%3};"
                 : "+f"(c[0]), "+f"(c[1]), "+f"(c[2]), "+f"(c[3])
                 : "r"(a[0]), "r"(a[1]), "r"(a[2]), "r"(a[3]), "r"(b[0]), "r"(b[1]));
}
__device__ __forceinline__ void cp16(uint32_t dst, const void* src) {
    asm volatile("cp.async.ca.shared.global [%0], [%1], 16;" :: "r"(dst), "l"(src) : "memory");
}
__device__ __forceinline__ void cp_commit() {
    asm volatile("cp.async.commit_group;" ::: "memory");
}
template<int N> __device__ __forceinline__ void cp_wait() {
    asm volatile("cp.async.wait_group %0;" :: "n"(N) : "memory");
}

// ---------------- software grid barrier -------------------------------------
__device__ __forceinline__ void grid_sync() {
    __syncthreads();
    if (threadIdx.x == 0) {
        __threadfence();
        unsigned g = g_bar_gen;
        unsigned old = atomicInc(&g_bar_count, NCTA - 1);
        if (old == NCTA - 1) {
            __threadfence();
            g_bar_gen = g + 1;
        } else {
            while (g_bar_gen == g) { }
            __threadfence();
        }
    }
    __syncthreads();
}

// ---------------- generic fp32 GEMM: C[m,n] = sum_k A[m,k]*W[n,k] + bias[n] -
template<int BM, int TM>
__global__ __launch_bounds__(256) void gemm_f32(
    const float* __restrict__ A, const float* __restrict__ W,
    const float* __restrict__ bias,
    float* __restrict__ C, int M, int N, int K)
{
    constexpr int BN = 64, BK = 16, TN = 4;
    __shared__ float As[BK][BM];
    __shared__ float Bs[BK][BN];

    const int tid = threadIdx.x;
    const int tx = tid & 15;
    const int ty = tid >> 4;
    const int nb = blockIdx.x * BN;
    const int mb = blockIdx.y * BM;

    unsigned long long acc[TM / 2][TN];
#pragma unroll
    for (int i = 0; i < TM / 2; i++)
#pragma unroll
        for (int j = 0; j < TN; j++) acc[i][j] = 0ull;

    for (int k0 = 0; k0 < K; k0 += BK) {
#pragma unroll
        for (int i = 0; i < BM / 64; i++) {
            int idx = tid + i * 256;
            int r = idx >> 2;
            int kq = (idx & 3) << 2;
            float4 v = *reinterpret_cast<const float4*>(A + (size_t)(mb + r) * K + k0 + kq);
            As[kq + 0][r] = v.x; As[kq + 1][r] = v.y;
            As[kq + 2][r] = v.z; As[kq + 3][r] = v.w;
        }
        {
            int r = tid >> 2;
            int kq = (tid & 3) << 2;
            float4 v = *reinterpret_cast<const float4*>(W + (size_t)(nb + r) * K + k0 + kq);
            Bs[kq + 0][r] = v.x; Bs[kq + 1][r] = v.y;
            Bs[kq + 2][r] = v.z; Bs[kq + 3][r] = v.w;
        }
        __syncthreads();

#pragma unroll
        for (int k = 0; k < BK; k++) {
            unsigned long long a2[TM / 2];
#pragma unroll
            for (int i = 0; i < TM / 2; i++)
                a2[i] = *reinterpret_cast<const unsigned long long*>(&As[k][ty * TM + 2 * i]);
            float4 bv = *reinterpret_cast<const float4*>(&Bs[k][tx * TN]);
            unsigned long long b2[TN];
            b2[0] = pack2(bv.x, bv.x);
            b2[1] = pack2(bv.y, bv.y);
            b2[2] = pack2(bv.z, bv.z);
            b2[3] = pack2(bv.w, bv.w);
#pragma unroll
            for (int i = 0; i < TM / 2; i++)
#pragma unroll
                for (int j = 0; j < TN; j++)
                    ffma2(acc[i][j], a2[i], b2[j]);
        }
        __syncthreads();
    }

    const int n0 = nb + tx * TN;
    float4 bias4 = *reinterpret_cast<const float4*>(bias + n0);
#pragma unroll
    for (int i = 0; i < TM / 2; i++) {
        int m0 = mb + ty * TM + 2 * i;
        float lo[TN], hi[TN];
#pragma unroll
        for (int j = 0; j < TN; j++) unpack2(acc[i][j], lo[j], hi[j]);
        float4 r0 = make_float4(lo[0] + bias4.x, lo[1] + bias4.y,
                                lo[2] + bias4.z, lo[3] + bias4.w);
        float4 r1 = make_float4(hi[0] + bias4.x, hi[1] + bias4.y,
                                hi[2] + bias4.z, hi[3] + bias4.w);
        *reinterpret_cast<float4*>(C + (size_t)m0 * N + n0) = r0;
        *reinterpret_cast<float4*>(C + (size_t)(m0 + 1) * N + n0) = r1;
    }
}

// ---------------- persistent split-bf16 tensor-core LSTM recurrence ---------
// 128 CTAs x 128 threads. CTA owns 8 hidden cols j0..j0+7 (x4 gates = 32 gemm
// cols) for all 128 batch rows. Whh hi/lo slice resident in smem (160 KB,
// stride 40 bf16 for conflict-free ldmatrix). h kept in gmem as bf16 hi/lo
// planes, staged per 32-k chunk via cp.async double buffering.
// Gates = h@Whh^T via mma.m16n8k16: C += Ahi*Bhi + Alo*Bhi + Ahi*Blo (fp32 acc).
#define WSTRIDE 40                       // bf16 elems per W smem row (80 B)
#define WBYTES  (1024 * WSTRIDE * 2)     // 81920 per matrix
#define AMAT    (128 * WSTRIDE * 2)      // 10240 bytes per A chunk matrix
#define ABUFB   (2 * AMAT)               // hi+lo per buffer
#define SMEM_TOTAL (2 * WBYTES + 2 * ABUFB)  // 204800 B

__global__ void __launch_bounds__(128, 1) lstm_recur(
    const float* __restrict__ xproj, const float* __restrict__ Whh,
    const float* __restrict__ bhh, float* __restrict__ hs)
{
    extern __shared__ char sm[];
    __nv_bfloat16* Whi = (__nv_bfloat16*)sm;
    __nv_bfloat16* Wlo = (__nv_bfloat16*)(sm + WBYTES);
    char* Ab = sm + 2 * WBYTES;          // A bufs: buf*ABUFB, lo at +AMAT
    const uint32_t abase = s2u(Ab);

    const int tid  = threadIdx.x;
    const int lane = tid & 31;
    const int w    = tid >> 5;
    const int wbase = w * 32;            // batch rows owned by this warp
    const int j0 = blockIdx.x * 8;

    // ---- load + split Whh slice into smem: Whi/Wlo[k][col], col = g*8+jj ----
    {
        int rcol = tid >> 2;             // 0..31
        int g = rcol >> 3, jj = rcol & 7;
        const float* wr = Whh + (size_t)(g * HH + j0 + jj) * HH;
        for (int q = 0; q < 64; q++) {
            int k = ((tid & 3) << 2) + q * 16;
            float4 v = *reinterpret_cast<const float4*>(wr + k);
            float vv[4] = {v.x, v.y, v.z, v.w};
#pragma unroll
            for (int e = 0; e < 4; e++) {
                __nv_bfloat16 hi = __float2bfloat16(vv[e]);
                __nv_bfloat16 lo = __float2bfloat16(vv[e] - __bfloat162float(hi));
                Whi[(k + e) * WSTRIDE + rcol] = hi;
                Wlo[(k + e) * WSTRIDE + rcol] = lo;
            }
        }
    }

    // bias (per lane: j pair), c state
    const int jp = j0 + (lane & 3) * 2;
    float bgf[4][2];
#pragma unroll
    for (int g = 0; g < 4; g++) {
        float2 bv = *reinterpret_cast<const float2*>(bhh + g * HH + jp);
        bgf[g][0] = bv.x; bgf[g][1] = bv.y;
    }
    float cst[2][2][2];
#pragma unroll
    for (int a = 0; a < 2; a++)
#pragma unroll
        for (int b = 0; b < 2; b++)
#pragma unroll
            for (int d = 0; d < 2; d++) cst[a][b][d] = 0.0f;

    // zero h buffer 0 (this CTA zeroes batch row = blockIdx.x)
    {
        uint32_t* zh = (uint32_t*)g_hhi + (size_t)blockIdx.x * 512;
        uint32_t* zl = (uint32_t*)g_hlo + (size_t)blockIdx.x * 512;
        for (int i = tid; i < 512; i += 128) { zh[i] = 0u; zl[i] = 0u; }
    }
    grid_sync();   // W smem + h0 visible

    for (int t = 0; t < TT; t++) {
        const char* hhb = (const char*)(g_hhi + (size_t)(t & 1) * (BB * HH));
        const char* hlb = (const char*)(g_hlo + (size_t)(t & 1) * (BB * HH));

        float cf[2][4][4];
#pragma unroll
        for (int mt = 0; mt < 2; mt++)
#pragma unroll
            for (int nt = 0; nt < 4; nt++)
#pragma unroll
                for (int e = 0; e < 4; e++) cf[mt][nt][e] = 0.0f;

        // ---- stage chunk 0 ----
        {
#pragma unroll
            for (int p = 0; p < 4; p++) {
                int ttk = tid + p * 128;
                int row = ttk >> 2, seg = ttk & 3;
                uint32_t d = abase + row * 80 + seg * 16;
                const char* s = hhb + row * 2048 + seg * 16;
                cp16(d, s);
                cp16(d + AMAT, hlb + row * 2048 + seg * 16);
            }
            cp_commit();
        }

        for (int kc = 0; kc < 32; kc++) {
            const int bf = kc & 1;
            if (kc < 31) {
#pragma unroll
                for (int p = 0; p < 4; p++) {
                    int ttk = tid + p * 128;
                    int row = ttk >> 2, seg = ttk & 3;
                    uint32_t d = abase + (bf ^ 1) * ABUFB + row * 80 + seg * 16;
                    const char* s = hhb + row * 2048 + (kc + 1) * 64 + seg * 16;
                    cp16(d, s);
                    cp16(d + AMAT, hlb + row * 2048 + (kc + 1) * 64 + seg * 16);
                }
                cp_commit();
                cp_wait<1>();
            } else {
                cp_wait<0>();
            }
            __syncthreads();

            const char* Abuf = Ab + bf * ABUFB;
#pragma unroll
            for (int ks = 0; ks < 2; ks++) {
                const int kk = kc * 32 + ks * 16;    // global k (W smem)
                const int kl = ks * 16;              // local k (A buf)

                // B fragments (shared across m-tiles)
                uint32_t bh[4][2], bl[4][2];
                {
                    int row = kk + (lane & 7) + ((lane & 8) ? 8 : 0);
                    int nc = ((lane & 16) ? 8 : 0);
                    uint32_t r4[4];
                    ldsm_x4_t(r4, s2u(Whi + row * WSTRIDE + nc));
                    bh[0][0] = r4[0]; bh[0][1] = r4[1]; bh[1][0] = r4[2]; bh[1][1] = r4[3];
                    ldsm_x4_t(r4, s2u(Whi + row * WSTRIDE + nc + 16));
                    bh[2][0] = r4[0]; bh[2][1] = r4[1]; bh[3][0] = r4[2]; bh[3][1] = r4[3];
                    ldsm_x4_t(r4, s2u(Wlo + row * WSTRIDE + nc));
                    bl[0][0] = r4[0]; bl[0][1] = r4[1]; bl[1][0] = r4[2]; bl[1][1] = r4[3];
                    ldsm_x4_t(r4, s2u(Wlo + row * WSTRIDE + nc + 16));
                    bl[2][0] = r4[0]; bl[2][1] = r4[1]; bl[3][0] = r4[2]; bl[3][1] = r4[3];
                }

#pragma unroll
                for (int mt = 0; mt < 2; mt++) {
                    int r = wbase + mt * 16 + (lane & 15);
                    int kcl = kl + ((lane & 16) ? 8 : 0);
                    uint32_t ah[4], al[4];
                    ldsm_x4(ah, abase + bf * ABUFB + r * 80 + kcl * 2);
                    ldsm_x4(al, abase + bf * ABUFB + AMAT + r * 80 + kcl * 2);
#pragma unroll
                    for (int nt = 0; nt < 4; nt++) {
                        mma_bf16(cf[mt][nt], ah, bh[nt]);
                        mma_bf16(cf[mt][nt], al, bh[nt]);
                        mma_bf16(cf[mt][nt], ah, bl[nt]);
                    }
                }
            }
            __syncthreads();
        }

        // ---- epilogue + pointwise ----
        const float* xp = xproj + (size_t)t * BB * GG;
        float* hst = hs + (size_t)t * BB * HH;
        unsigned short* nhh = g_hhi + (size_t)((t + 1) & 1) * (BB * HH);
        unsigned short* nhl = g_hlo + (size_t)((t + 1) & 1) * (BB * HH);
#pragma unroll
        for (int mt = 0; mt < 2; mt++)
#pragma unroll
        for (int rr = 0; rr < 2; rr++) {
            int b = wbase + mt * 16 + rr * 8 + (lane >> 2);
            const float* xb = xp + (size_t)b * GG + jp;
            float hv[2];
#pragma unroll
            for (int jj = 0; jj < 2; jj++) {
                int ci = rr * 2 + jj;
                float gi = cf[mt][0][ci] + xb[0 * HH + jj] + bgf[0][jj];
                float gf = cf[mt][1][ci] + xb[1 * HH + jj] + bgf[1][jj];
                float gg = cf[mt][2][ci] + xb[2 * HH + jj] + bgf[2][jj];
                float go = cf[mt][3][ci] + xb[3 * HH + jj] + bgf[3][jj];
                float cv = fsig(gf) * cst[mt][rr][jj] + fsig(gi) * ftanh(gg);
                cst[mt][rr][jj] = cv;
                hv[jj] = fsig(go) * ftanh(cv);
            }
            *reinterpret_cast<float2*>(hst + (size_t)b * HH + jp) = make_float2(hv[0], hv[1]);
            __nv_bfloat16 h0 = __float2bfloat16(hv[0]);
            __nv_bfloat16 h1 = __float2bfloat16(hv[1]);
            __nv_bfloat16 l0 = __float2bfloat16(hv[0] - __bfloat162float(h0));
            __nv_bfloat16 l1 = __float2bfloat16(hv[1] - __bfloat162float(h1));
            uint32_t ph = (uint32_t)__bfloat16_as_ushort(h0) |
                          ((uint32_t)__bfloat16_as_ushort(h1) << 16);
            uint32_t pl = (uint32_t)__bfloat16_as_ushort(l0) |
                          ((uint32_t)__bfloat16_as_ushort(l1) << 16);
            *reinterpret_cast<uint32_t*>(nhh + (size_t)b * HH + jp) = ph;
            *reinterpret_cast<uint32_t*>(nhl + (size_t)b * HH + jp) = pl;
        }
        grid_sync();
    }
}

// ---------------- row-wise log_softmax over last dim (II=256), in place -----
__global__ void log_softmax_k(float* __restrict__ out) {
    int row = blockIdx.x;
    float* p = out + (size_t)row * II;
    int tid = threadIdx.x;
    int lane = tid & 31, wid = tid >> 5;
    float v = p[tid];

    __shared__ float redm[8];
    __shared__ float reds[8];

    float m = v;
#pragma unroll
    for (int o = 16; o > 0; o >>= 1) m = fmaxf(m, __shfl_xor_sync(0xffffffffu, m, o));
    if (lane == 0) redm[wid] = m;
    __syncthreads();
    float mx = redm[0];
#pragma unroll
    for (int i = 1; i < 8; i++) mx = fmaxf(mx, redm[i]);

    float e = expf(v - mx);
    float s = e;
#pragma unroll
    for (int o = 16; o > 0; o >>= 1) s += __shfl_xor_sync(0xffffffffu, s, o);
    if (lane == 0) reds[wid] = s;
    __syncthreads();
    float tot = 0.0f;
#pragma unroll
    for (int i = 0; i < 8; i++) tot += reds[i];

    p[tid] = v - mx - logf(tot);
}

// ---------------- launch (4 graph nodes) ------------------------------------
extern "C" void kernel_launch(void* const* d_in, const int* in_sizes, int n_in,
                              void* d_out, int out_size)
{
    const float* inp  = (const float*)d_in[0];
    const float* Wxh  = (const float*)d_in[1];
    const float* bxh  = (const float*)d_in[2];
    const float* Whh  = (const float*)d_in[3];
    const float* bhh  = (const float*)d_in[4];
    const float* Wout = (const float*)d_in[5];
    const float* bout = (const float*)d_in[6];
    float* out = (float*)d_out;

    float *xproj, *hs;
    cudaGetSymbolAddress((void**)&xproj, g_xproj);
    cudaGetSymbolAddress((void**)&hs,    g_hs);

    static bool attr_set = false;
    if (!attr_set) {
        cudaFuncSetAttribute(lstm_recur,
                             cudaFuncAttributeMaxDynamicSharedMemorySize,
                             SMEM_TOTAL);
        attr_set = true;
    }

    // 1) x projection: [T*B, 4H] = [T*B, IN] @ Wxh^T + bxh
    gemm_f32<128, 8><<<dim3(GG / 64, (TT * BB) / 128), 256>>>(
        inp, Wxh, bxh, xproj, TT * BB, GG, II);

    // 2) persistent tensor-core recurrence
    lstm_recur<<<NCTA, 128, SMEM_TOTAL>>>(xproj, Whh, bhh, hs);

    // 3) output projection into d_out
    gemm_f32<128, 8><<<dim3(II / 64, (TT * BB) / 128), 256>>>(
        hs, Wout, bout, out, TT * BB, II, HH);

    // 4) in-place log_softmax
    log_softmax_k<<<TT * BB, 256>>>(out);
}